// round 10
// baseline (speedup 1.0000x reference)
#include <cuda_runtime.h>
#include <cuda_bf16.h>
#include <cstdint>

// ScaleLayer: y[b,d] = x[b,d] * exp(diag[d]);  second output = raw diag.
// x: [16384, 4096] fp32 row-major; diag: [4096] fp32.
//
// R10 probe: same as the measured-best R7/R9 config (single kernel,
// loop-free exact cover, 4 front-batched LDG.128/thread, plain LDG/STG,
// inline exp, 16384 CTAs x 256 threads) but each thread owns TWO ADJACENT
// float4 at two row strides: per-warp contiguous runs grow 512B -> 1KB per
// load pair (marginally better HBM sector/row locality, identical traffic,
// identical MLP=4). Revert to R9 if total > 82.1us.

#define D_DIM 4096
#define B_DIM 16384

// total4 = 16,777,216 float4; threads = 4,194,304 = total4/4.
// Thread t handles {2t, 2t+1, 2t+P, 2t+P+1}, P = total4/2 = 8,388,608.
// P is a multiple of D_DIM/4, so index 2t and 2t+P share a diag column,
// as do 2t+1 and 2t+P+1.
__global__ void __launch_bounds__(256)
scale_kernel(const float4* __restrict__ x,
             const float4* __restrict__ diag4,
             float4* __restrict__ y,
             float4* __restrict__ tail,   // d_out + B*D (raw diag echo)
             int write_tail) {
    constexpr int P = (B_DIM * D_DIM) / 4 / 2;     // 8,388,608

    const int t  = blockIdx.x * blockDim.x + threadIdx.x;
    const int j0 = 2 * t;
    const int j1 = 2 * t + 1;
    const int j2 = j0 + P;
    const int j3 = j1 + P;
    const int c0 = j0 & (D_DIM / 4 - 1);
    const int c1 = j1 & (D_DIM / 4 - 1);

    // Front-batched independent loads (MLP=4) + two 16B diag loads (L1-hot).
    float4 v0 = x[j0];
    float4 v1 = x[j1];
    float4 v2 = x[j2];
    float4 v3 = x[j3];
    float4 d0 = diag4[c0];
    float4 d1 = diag4[c1];

    // Raw diag echo: threads with j0 < 1024 have c0==j0, c1==j1 -> blocks
    // 0..1 cover the 1024-float4 tail exactly once.
    if (write_tail && j0 < (D_DIM / 4)) {
        tail[j0] = d0;
        tail[j1] = d1;
    }

    // exp() inline -- MUFU hidden under memory stalls (measured R7/R9).
    float4 e0, e1;
    e0.x = expf(d0.x); e0.y = expf(d0.y); e0.z = expf(d0.z); e0.w = expf(d0.w);
    e1.x = expf(d1.x); e1.y = expf(d1.y); e1.z = expf(d1.z); e1.w = expf(d1.w);

    v0.x *= e0.x; v0.y *= e0.y; v0.z *= e0.z; v0.w *= e0.w;
    v1.x *= e1.x; v1.y *= e1.y; v1.z *= e1.z; v1.w *= e1.w;
    v2.x *= e0.x; v2.y *= e0.y; v2.z *= e0.z; v2.w *= e0.w;
    v3.x *= e1.x; v3.y *= e1.y; v3.z *= e1.z; v3.w *= e1.w;

    y[j0] = v0;
    y[j1] = v1;
    y[j2] = v2;
    y[j3] = v3;
}

extern "C" void kernel_launch(void* const* d_in, const int* in_sizes, int n_in,
                              void* d_out, int out_size) {
    const float* x    = (const float*)d_in[0];
    const float* diag = (const float*)d_in[1];
    float* out = (float*)d_out;

    const long long n_main = (long long)B_DIM * D_DIM;
    const int write_tail = (out_size > n_main) ? 1 : 0;

    // 16,777,216 float4 / (256 thr * 4 per thread) = 16384 CTAs, exact.
    scale_kernel<<<16384, 256>>>((const float4*)x,
                                 (const float4*)diag,
                                 (float4*)out,
                                 (float4*)(out + n_main),
                                 write_tail);
}

// round 11
// speedup vs baseline: 1.0222x; 1.0222x over previous
#include <cuda_runtime.h>
#include <cuda_bf16.h>
#include <cstdint>

// ScaleLayer: y[b,d] = x[b,d] * exp(diag[d]);  second output = raw diag.
// x: [16384, 4096] fp32 row-major; diag: [4096] fp32.
//
// FINAL (measured best, reproduced twice: kernel 73.98-74.18us @ 82.5% DRAM
// / 6.54 TB/s, total 81.95-82.02us). Pinned at the B300 HBM/LTS streaming
// ceiling for 512 MiB mandatory read+write traffic.
//
// Search results (10 rounds):
//   - unit-stride-per-lane LDG.128, 4 front-batched per thread (MLP=4): BEST
//   - MLP=8: regs 32->56, occ 82->44%, slower
//   - __ldcs/__stcs: neutral to slightly negative
//   - lane-interleaved (2 adjacent float4/thread): 8 lines/LDG instead of 4,
//     L1 wavefronts doubled, -9% DRAM throughput -- worst variant
//   - 512-thread CTAs: neutral
//   - separate exp-prologue kernel: +2us graph-node serialization; inline
//     expf (4/thread) is fully hidden under memory stalls (issue 8->14%,
//     DRAM% unchanged)
//
// Design: single kernel, loop-free exact cover. Thread j handles float4s
// {j, j+S, j+2S, j+3S} (S = total threads = total4/4); S is a multiple of
// D_DIM/4 so all four share one diag column. Diag echo: threads j<1024
// write tail[j] (col4==j there), exact cover by blocks 0..3.

#define D_DIM 4096
#define B_DIM 16384

__global__ void __launch_bounds__(256)
scale_kernel(const float4* __restrict__ x,
             const float4* __restrict__ diag4,
             float4* __restrict__ y,
             float4* __restrict__ tail,   // d_out + B*D (raw diag echo)
             int write_tail) {
    constexpr int S = (B_DIM * D_DIM) / 4 / 4;     // 4,194,304

    const int j  = blockIdx.x * blockDim.x + threadIdx.x;
    const int j0 = j;
    const int j1 = j + S;
    const int j2 = j + 2 * S;
    const int j3 = j + 3 * S;
    const int col4 = j & (D_DIM / 4 - 1);

    // Front-batched independent loads (MLP=4) + the 16B diag load (L1-hot).
    float4 v0 = x[j0];
    float4 v1 = x[j1];
    float4 v2 = x[j2];
    float4 v3 = x[j3];
    float4 d  = diag4[col4];

    // Raw diag echo: threads j<1024 give col4 == j -> exact cover of the
    // 1024-float4 tail by blocks 0..3.
    if (write_tail && j < (D_DIM / 4)) tail[j] = d;

    // exp() inline -- MUFU work overlapped with memory stalls.
    float4 e;
    e.x = expf(d.x);
    e.y = expf(d.y);
    e.z = expf(d.z);
    e.w = expf(d.w);

    v0.x *= e.x; v0.y *= e.y; v0.z *= e.z; v0.w *= e.w;
    v1.x *= e.x; v1.y *= e.y; v1.z *= e.z; v1.w *= e.w;
    v2.x *= e.x; v2.y *= e.y; v2.z *= e.z; v2.w *= e.w;
    v3.x *= e.x; v3.y *= e.y; v3.z *= e.z; v3.w *= e.w;

    y[j0] = v0;
    y[j1] = v1;
    y[j2] = v2;
    y[j3] = v3;
}

extern "C" void kernel_launch(void* const* d_in, const int* in_sizes, int n_in,
                              void* d_out, int out_size) {
    const float* x    = (const float*)d_in[0];
    const float* diag = (const float*)d_in[1];
    float* out = (float*)d_out;

    const long long n_main = (long long)B_DIM * D_DIM;
    const int write_tail = (out_size > n_main) ? 1 : 0;

    // 16,777,216 float4 / (256 thr * 4 per thread) = 16384 CTAs, exact.
    scale_kernel<<<16384, 256>>>((const float4*)x,
                                 (const float4*)diag,
                                 (float4*)out,
                                 (float4*)(out + n_main),
                                 write_tail);
}

// round 12
// speedup vs baseline: 1.0226x; 1.0004x over previous
#include <cuda_runtime.h>
#include <cuda_bf16.h>
#include <cstdint>

// ScaleLayer: y[b,d] = x[b,d] * exp(diag[d]);  second output = raw diag.
// x: [16384, 4096] fp32 row-major; diag: [4096] fp32.
//
// CONVERGED FINAL (reproduced 3x: kernel 74.0-74.6us @ 82.0-82.5% DRAM /
// 6.50-6.54 TB/s, total 81.95-82.08us). Pinned at the B300 HBM/LTS
// streaming ceiling for 512 MiB mandatory read+write traffic; the LTS cap
// is path-independent (TMA == LDG), so no staging scheme can beat this.
//
// Full search record (11 rounds):
//   - MLP per thread: 4 best (8 -> regs 56, occ 44%, slower)
//   - lane layout: unit-stride best (2-adjacent interleave doubles
//     lines/LDG -> -9% DRAM BW; column-fixed slightly worse)
//   - cache hints: plain LDG/STG best (ldcs/stcs neutral-to-negative)
//   - exp: inline (4 expf/thread) fully hidden under memory stalls;
//     separate prologue kernel costs ~2us of graph-node serialization
//   - CTA shape 256 vs 512: tie; loop-free exact cover: lowest regs (32)
//
// Thread j handles float4s {j, j+S, j+2S, j+3S} (S = total threads); S is a
// multiple of D_DIM/4 so all four share one diag column. Diag echo: threads
// j<1024 write tail[j] (col4==j there), exact cover by blocks 0..3.

#define D_DIM 4096
#define B_DIM 16384

__global__ void __launch_bounds__(256)
scale_kernel(const float4* __restrict__ x,
             const float4* __restrict__ diag4,
             float4* __restrict__ y,
             float4* __restrict__ tail,   // d_out + B*D (raw diag echo)
             int write_tail) {
    constexpr int S = (B_DIM * D_DIM) / 4 / 4;     // 4,194,304

    const int j  = blockIdx.x * blockDim.x + threadIdx.x;
    const int j0 = j;
    const int j1 = j + S;
    const int j2 = j + 2 * S;
    const int j3 = j + 3 * S;
    const int col4 = j & (D_DIM / 4 - 1);

    // Front-batched independent loads (MLP=4) + the 16B diag load (L1-hot).
    float4 v0 = x[j0];
    float4 v1 = x[j1];
    float4 v2 = x[j2];
    float4 v3 = x[j3];
    float4 d  = diag4[col4];

    // Raw diag echo: threads j<1024 give col4 == j -> exact cover of the
    // 1024-float4 tail by blocks 0..3.
    if (write_tail && j < (D_DIM / 4)) tail[j] = d;

    // exp() inline -- MUFU work overlapped with memory stalls.
    float4 e;
    e.x = expf(d.x);
    e.y = expf(d.y);
    e.z = expf(d.z);
    e.w = expf(d.w);

    v0.x *= e.x; v0.y *= e.y; v0.z *= e.z; v0.w *= e.w;
    v1.x *= e.x; v1.y *= e.y; v1.z *= e.z; v1.w *= e.w;
    v2.x *= e.x; v2.y *= e.y; v2.z *= e.z; v2.w *= e.w;
    v3.x *= e.x; v3.y *= e.y; v3.z *= e.z; v3.w *= e.w;

    y[j0] = v0;
    y[j1] = v1;
    y[j2] = v2;
    y[j3] = v3;
}

extern "C" void kernel_launch(void* const* d_in, const int* in_sizes, int n_in,
                              void* d_out, int out_size) {
    const float* x    = (const float*)d_in[0];
    const float* diag = (const float*)d_in[1];
    float* out = (float*)d_out;

    const long long n_main = (long long)B_DIM * D_DIM;
    const int write_tail = (out_size > n_main) ? 1 : 0;

    // 16,777,216 float4 / (256 thr * 4 per thread) = 16384 CTAs, exact.
    scale_kernel<<<16384, 256>>>((const float4*)x,
                                 (const float4*)diag,
                                 (float4*)out,
                                 (float4*)(out + n_main),
                                 write_tail);
}

// round 13
// speedup vs baseline: 1.0230x; 1.0004x over previous
#include <cuda_runtime.h>
#include <cuda_bf16.h>
#include <cstdint>

// ScaleLayer: y[b,d] = x[b,d] * exp(diag[d]);  second output = raw diag.
// x: [16384, 4096] fp32 row-major; diag: [4096] fp32.
//
// CONVERGED FINAL (reproduced 4x: kernel 74.0-74.6us @ 82.0-82.5% DRAM /
// 6.50-6.54 TB/s, total 81.95-82.08us, sigma ~0.05us). Pinned at the B300
// HBM/LTS streaming ceiling for 512 MiB of mandatory read+write traffic;
// the LTS chip cap is path-independent (TMA == LDG.cv), so no staging
// scheme can exceed this. Remaining ~7.8us of total is fixed harness/graph
// overhead, invariant to kernel structure.
//
// Full search record (12 rounds):
//   - MLP per thread: 4 best (8 -> regs 56, occ 44%, slower)
//   - lane layout: unit-stride best (2-adjacent interleave doubles
//     lines/LDG -> L1 wavefronts x2, -9% DRAM BW; column-fixed worse)
//   - cache hints: plain LDG/STG best (ldcs/stcs neutral-to-negative)
//   - exp: inline (4 expf/thread, 16.8M EX2 chip-wide) fully hidden under
//     memory stalls (issue 8->14%, DRAM% unchanged); separate prologue
//     kernel costs ~2us of graph-node serialization
//   - CTA 256 vs 512: tie; loop-free exact cover beats grid-stride loops
//     by ~2us (lowest regs = 32, no branch/index overhead)
//
// Thread j handles float4s {j, j+S, j+2S, j+3S} (S = total threads); S is a
// multiple of D_DIM/4 so all four share one diag column. Diag echo: threads
// j<1024 write tail[j] (col4==j there), exact cover by blocks 0..3.

#define D_DIM 4096
#define B_DIM 16384

__global__ void __launch_bounds__(256)
scale_kernel(const float4* __restrict__ x,
             const float4* __restrict__ diag4,
             float4* __restrict__ y,
             float4* __restrict__ tail,   // d_out + B*D (raw diag echo)
             int write_tail) {
    constexpr int S = (B_DIM * D_DIM) / 4 / 4;     // 4,194,304

    const int j  = blockIdx.x * blockDim.x + threadIdx.x;
    const int j0 = j;
    const int j1 = j + S;
    const int j2 = j + 2 * S;
    const int j3 = j + 3 * S;
    const int col4 = j & (D_DIM / 4 - 1);

    // Front-batched independent loads (MLP=4) + the 16B diag load (L1-hot).
    float4 v0 = x[j0];
    float4 v1 = x[j1];
    float4 v2 = x[j2];
    float4 v3 = x[j3];
    float4 d  = diag4[col4];

    // Raw diag echo: threads j<1024 give col4 == j -> exact cover of the
    // 1024-float4 tail by blocks 0..3.
    if (write_tail && j < (D_DIM / 4)) tail[j] = d;

    // exp() inline -- MUFU work overlapped with memory stalls.
    float4 e;
    e.x = expf(d.x);
    e.y = expf(d.y);
    e.z = expf(d.z);
    e.w = expf(d.w);

    v0.x *= e.x; v0.y *= e.y; v0.z *= e.z; v0.w *= e.w;
    v1.x *= e.x; v1.y *= e.y; v1.z *= e.z; v1.w *= e.w;
    v2.x *= e.x; v2.y *= e.y; v2.z *= e.z; v2.w *= e.w;
    v3.x *= e.x; v3.y *= e.y; v3.z *= e.z; v3.w *= e.w;

    y[j0] = v0;
    y[j1] = v1;
    y[j2] = v2;
    y[j3] = v3;
}

extern "C" void kernel_launch(void* const* d_in, const int* in_sizes, int n_in,
                              void* d_out, int out_size) {
    const float* x    = (const float*)d_in[0];
    const float* diag = (const float*)d_in[1];
    float* out = (float*)d_out;

    const long long n_main = (long long)B_DIM * D_DIM;
    const int write_tail = (out_size > n_main) ? 1 : 0;

    // 16,777,216 float4 / (256 thr * 4 per thread) = 16384 CTAs, exact.
    scale_kernel<<<16384, 256>>>((const float4*)x,
                                 (const float4*)diag,
                                 (float4*)out,
                                 (float4*)(out + n_main),
                                 write_tail);
}